// round 6
// baseline (speedup 1.0000x reference)
#include <cuda_runtime.h>
#include <cuda_bf16.h>

#define L1N 16
#define DIN 1536
#define COUNT 8
#define L3N 64
#define BMAX 16384
#define CTA_SAMPLES 128
#define THREADS 512
#define CK 64                   // k per chunk
#define NCH (DIN / CK)          // 24
#define XST 68                  // x smem row stride (floats)
#define RST 20                  // reduction row stride
#define HB 64

// ---- device scratch ----
__device__ float g_wsum[COUNT * DIN * L1N];   // [b][k][16]
__device__ float g_bsum[COUNT * L1N];
__device__ float g_w2p[COUNT * L3N * 32];
__device__ int   g_bh[HB * COUNT];
__device__ int   g_aoff[COUNT + 1];
__device__ int   g_order[BMAX + COUNT * CTA_SAMPLES];

// ---------------- prep: 192 blocks = 8 buckets x 24 k-tiles(64), transpose, pad W2, hist ----------------
__global__ void k_prep(const float* __restrict__ W1, const float* __restrict__ b1,
                       const float* __restrict__ Wf, const float* __restrict__ bf,
                       const float* __restrict__ W2, const int* __restrict__ ls,
                       int n, int hb) {
    __shared__ float tile[16 * 68];
    int t = threadIdx.x;
    int bucket = blockIdx.x / 24;
    int kt = blockIdx.x - bucket * 24;   // 64-k tile

    // load 16 x 64 tile, coalesced along k
#pragma unroll
    for (int r = 0; r < 4; ++r) {
        int idx = t + 256 * r;          // 0..1023
        int row = idx >> 6;             // o
        int col = idx & 63;             // k in tile
        float a = W1[(size_t)(bucket * L1N + row) * DIN + kt * 64 + col]
                + Wf[(size_t)row * DIN + kt * 64 + col];
        tile[row * 68 + col] = a;
    }
    __syncthreads();

    // write transposed [k][16] as float4, fully coalesced
    {
        float4* dst = (float4*)(g_wsum + (size_t)bucket * (DIN * L1N));
        int k = t >> 2;                  // 0..63
        int o4 = t & 3;
        float4 v;
        v.x = tile[(4 * o4 + 0) * 68 + k];
        v.y = tile[(4 * o4 + 1) * 68 + k];
        v.z = tile[(4 * o4 + 2) * 68 + k];
        v.w = tile[(4 * o4 + 3) * 68 + k];
        dst[(kt * 64 + k) * 4 + o4] = v;
    }

    int tidg = blockIdx.x * 256 + t;
    if (tidg < COUNT * L3N * 32) {
        int b = tidg >> 11;
        int j = (tidg >> 5) & 63;
        int i = tidg & 31;
        g_w2p[tidg] = (i < 30) ? W2[(b * L3N + j) * 30 + i] : 0.0f;
    }
    if (tidg < COUNT * L1N) {
        int b = tidg >> 4, o = tidg & 15;
        g_bsum[tidg] = b1[b * L1N + o] + bf[o];
    }
    if ((int)blockIdx.x < hb) {
        __shared__ int sh[COUNT];
        if (t < COUNT) sh[t] = 0;
        __syncthreads();
        int i = blockIdx.x * 256 + t;
        if (i < n) {
            int b = ls[i];
            unsigned act = __activemask();
            unsigned m = __match_any_sync(act, b);
            int lane = t & 31;
            int leader = __ffs(m) - 1;
            if (lane == leader) atomicAdd(&sh[b], __popc(m));
        }
        __syncthreads();
        if (t < COUNT) g_bh[blockIdx.x * COUNT + t] = sh[t];
    }
}

// ---------------- scatter with inline scan ----------------
__global__ void k_scatter(const int* __restrict__ ls, int n, int hb) {
    __shared__ int sh[HB * COUNT];
    __shared__ int s_aoff[COUNT + 1];
    __shared__ int s_cnt[COUNT];
    __shared__ int cur[COUNT];
    int t = threadIdx.x;
    for (int i = t; i < hb * COUNT; i += 256) sh[i] = g_bh[i];
    __syncthreads();
    if (t < COUNT) {
        int tot = 0;
        for (int j = 0; j < hb; ++j) tot += sh[j * COUNT + t];
        s_cnt[t] = tot;
    }
    __syncthreads();
    if (t == 0) {
        int off = 0;
        for (int b = 0; b < COUNT; ++b) {
            s_aoff[b] = off;
            off += (s_cnt[b] + CTA_SAMPLES - 1) & ~(CTA_SAMPLES - 1);
        }
        s_aoff[COUNT] = off;
        if (blockIdx.x == 0)
            for (int b = 0; b <= COUNT; ++b) g_aoff[b] = s_aoff[b];
    }
    __syncthreads();
    if (t < COUNT) {
        int run = s_aoff[t];
        for (int j = 0; j < (int)blockIdx.x; ++j) run += sh[j * COUNT + t];
        cur[t] = run;
    }
    __syncthreads();
    if (blockIdx.x == 0) {
        for (int b = 0; b < COUNT; ++b) {
            int s = s_aoff[b] + s_cnt[b];
            int e = s_aoff[b + 1];
            for (int i = s + t; i < e; i += 256) g_order[i] = -1;
        }
    }
    int i = blockIdx.x * 256 + t;
    if (i < n) {
        int b = ls[i];
        unsigned act = __activemask();
        unsigned m = __match_any_sync(act, b);
        int lane = t & 31;
        int leader = __ffs(m) - 1;
        int rank = __popc(m & ((1u << lane) - 1u));
        int base = 0;
        if (lane == leader) base = atomicAdd(&cur[b], __popc(m));
        base = __shfl_sync(act, base, leader);
        g_order[base + rank] = i;
    }
}

// ---------------- main: 512 thr, 4 samples/lane, 16 k-slices of 4 ----------------
#define XS_WORDS 20480
#define RED2_OFF 0   // red2 gets its own region
#define SMEM_WORDS (24576 + 2048 + 16 + 64 + 64 + 128 + 512 + XS_WORDS)
#define SMEM_BYTES (SMEM_WORDS * 4)

__global__ void __launch_bounds__(THREADS, 1) k_main(const float* __restrict__ x,
                                                     const float* __restrict__ b2,
                                                     const float* __restrict__ Wo,
                                                     const float* __restrict__ bo,
                                                     float* __restrict__ out) {
    extern __shared__ float sm[];
    float* ws   = sm;                   // [k][16] ; reused as reduction slices 0..7
    float* w2s  = ws + 24576;           // [j][32]
    float* bs   = w2s + 2048;
    float* b2s  = bs + 16;
    float* wos  = b2s + 64;
    int* sidx_s = (int*)(wos + 64);     // 128
    float* red2 = (float*)(sidx_s + 128);  // 512
    float* xs   = red2 + 512;           // XS_WORDS ; reused as reduction slices 8..15

    int tid = threadIdx.x;
    int base = blockIdx.x * CTA_SAMPLES;
    if (base >= g_aoff[COUNT]) return;

    int b = 0;
#pragma unroll
    for (int t = 1; t < COUNT; ++t)
        if (base >= g_aoff[t]) b = t;

    // stage weights
    {
        const float4* src = (const float4*)(g_wsum + (size_t)b * (DIN * L1N));
        float4* dst = (float4*)ws;
#pragma unroll
        for (int r = 0; r < 12; ++r) dst[tid + r * THREADS] = src[tid + r * THREADS];
    }
    ((float4*)w2s)[tid] = ((const float4*)(g_w2p + (size_t)b * (L3N * 32)))[tid];
    if (tid < 16) bs[tid] = g_bsum[b * L1N + tid];
    else if (tid >= 32 && tid < 96) b2s[tid - 32] = b2[b * L3N + (tid - 32)];
    else if (tid >= 96 && tid < 160) wos[tid - 96] = Wo[b * L3N + (tid - 96)];
    if (tid < 128) sidx_s[tid] = g_order[base + tid];
    __syncthreads();

    // ---- loader assignment (proven: 16 threads/row, consecutive float4) ----
    const float4* p4[4];
    int ls_[4], lk_[4];
#pragma unroll
    for (int r = 0; r < 4; ++r) {
        int i = tid + THREADS * r;
        int s = i >> 4;
        int k4 = i & 15;
        ls_[r] = s; lk_[r] = k4;
        int sv = sidx_s[s];
        p4[r] = (const float4*)(x + (size_t)(sv >= 0 ? sv : 0) * DIN) + k4;
    }

    // ---- consumer mapping: warp wid -> k-slice of 4 within chunk; 4 samples/lane ----
    int wid = tid >> 5, lane = tid & 31;

    unsigned long long acc[32];   // [r][8 pairs]
#pragma unroll
    for (int i = 0; i < 32; ++i) acc[i] = 0ULL;

    const ulonglong2* wp = (const ulonglong2*)ws;

    float4 pf[4];
#pragma unroll
    for (int r = 0; r < 4; ++r) pf[r] = p4[r][0];

#pragma unroll 1
    for (int c = 0; c < NCH; ++c) {
        float* xb = xs + (c & 1) * (128 * XST);
#pragma unroll
        for (int r = 0; r < 4; ++r)
            *(float4*)(xb + ls_[r] * XST + lk_[r] * 4) = pf[r];
        __syncthreads();
        if (c + 1 < NCH) {
#pragma unroll
            for (int r = 0; r < 4; ++r) pf[r] = p4[r][(c + 1) * 16];
        }
        const float* xbase = xb + wid * 4;
        float4 xa[4];
#pragma unroll
        for (int r = 0; r < 4; ++r)
            xa[r] = *(const float4*)(xbase + (lane + 32 * r) * XST);
        int kg = c * CK + wid * 4;
#pragma unroll
        for (int t4 = 0; t4 < 4; ++t4) {
            const ulonglong2* wr = wp + (unsigned)(kg + t4) * 4;
            ulonglong2 w0 = wr[0], w1 = wr[1], w2 = wr[2], w3 = wr[3];
#pragma unroll
            for (int r = 0; r < 4; ++r) {
                float v = (t4 == 0) ? xa[r].x : (t4 == 1) ? xa[r].y
                        : (t4 == 2) ? xa[r].z : xa[r].w;
                unsigned long long d;
                asm("mov.b64 %0, {%1, %1};" : "=l"(d) : "f"(v));
                unsigned long long* a = acc + r * 8;
                asm("fma.rn.f32x2 %0, %1, %2, %0;" : "+l"(a[0]) : "l"(d), "l"(w0.x));
                asm("fma.rn.f32x2 %0, %1, %2, %0;" : "+l"(a[1]) : "l"(d), "l"(w0.y));
                asm("fma.rn.f32x2 %0, %1, %2, %0;" : "+l"(a[2]) : "l"(d), "l"(w1.x));
                asm("fma.rn.f32x2 %0, %1, %2, %0;" : "+l"(a[3]) : "l"(d), "l"(w1.y));
                asm("fma.rn.f32x2 %0, %1, %2, %0;" : "+l"(a[4]) : "l"(d), "l"(w2.x));
                asm("fma.rn.f32x2 %0, %1, %2, %0;" : "+l"(a[5]) : "l"(d), "l"(w2.y));
                asm("fma.rn.f32x2 %0, %1, %2, %0;" : "+l"(a[6]) : "l"(d), "l"(w3.x));
                asm("fma.rn.f32x2 %0, %1, %2, %0;" : "+l"(a[7]) : "l"(d), "l"(w3.y));
            }
        }
    }
    __syncthreads();

    // ---- 16-way k reduction: slice wid -> region (ws for 0..7, xs for 8..15) ----
    {
        float* regbase = (wid < 8) ? ws : xs;
        int q = wid & 7;
#pragma unroll
        for (int r = 0; r < 4; ++r) {
            int s = lane + 32 * r;
            float* br = regbase + (q * 128 + s) * RST;
#pragma unroll
            for (int p = 0; p < 8; ++p) {
                float lo, hi;
                asm("mov.b64 {%0, %1}, %2;" : "=f"(lo), "=f"(hi) : "l"(acc[r * 8 + p]));
                br[2 * p] = lo; br[2 * p + 1] = hi;
            }
        }
    }
    __syncthreads();

    // ---- tail: 4 j-groups x 128 samples ----
    int s2 = tid & 127;
    int jg = tid >> 7;
    float l1[16];
#pragma unroll
    for (int o = 0; o < 16; o += 4) {
        float4 v = *(const float4*)(bs + o);
#pragma unroll
        for (int q = 0; q < 8; ++q) {
            float4 r4 = *(const float4*)(ws + (q * 128 + s2) * RST + o);
            v.x += r4.x; v.y += r4.y; v.z += r4.z; v.w += r4.w;
            float4 r5 = *(const float4*)(xs + (q * 128 + s2) * RST + o);
            v.x += r5.x; v.y += r5.y; v.z += r5.z; v.w += r5.w;
        }
        l1[o] = v.x; l1[o + 1] = v.y; l1[o + 2] = v.z; l1[o + 3] = v.w;
    }

    const float C = 127.0f / 128.0f;
    float lx[32];
#pragma unroll
    for (int i = 0; i < 15; ++i) {
        float v = l1[i];
        float sq = (v * v) * C;
        lx[i]      = fminf(fmaxf(sq, 0.0f), 1.0f);
        lx[15 + i] = fminf(fmaxf(v, 0.0f), 1.0f);
    }
    lx[30] = 0.0f;
    lx[31] = 0.0f;

    float l3p = 0.0f;
#pragma unroll 2
    for (int jj = 0; jj < 16; ++jj) {
        int j = jg * 16 + jj;
        float ssum = b2s[j];
        const float4* wr2 = (const float4*)(w2s + j * 32);
#pragma unroll
        for (int p = 0; p < 8; ++p) {
            float4 wv = wr2[p];
            ssum = fmaf(lx[4 * p + 0], wv.x, ssum);
            ssum = fmaf(lx[4 * p + 1], wv.y, ssum);
            ssum = fmaf(lx[4 * p + 2], wv.z, ssum);
            ssum = fmaf(lx[4 * p + 3], wv.w, ssum);
        }
        float sc = fminf(fmaxf(ssum, 0.0f), 1.0f);
        l3p = fmaf(sc, wos[j], l3p);
    }
    red2[jg * 128 + s2] = l3p;
    __syncthreads();

    if (tid < 128) {
        int sv = sidx_s[tid];
        if (sv >= 0) {
            float l3 = red2[tid] + red2[128 + tid] + red2[256 + tid] + red2[384 + tid];
            out[sv] = l3 + bo[b] + l1[15];
        }
    }
}

// ---------------- launch ----------------
extern "C" void kernel_launch(void* const* d_in, const int* in_sizes, int n_in,
                              void* d_out, int out_size) {
    const float* x  = (const float*)d_in[0];
    const int*   ls = (const int*)d_in[1];
    const float* W1 = (const float*)d_in[2];
    const float* b1 = (const float*)d_in[3];
    const float* Wf = (const float*)d_in[4];
    const float* bf = (const float*)d_in[5];
    const float* W2 = (const float*)d_in[6];
    const float* b2 = (const float*)d_in[7];
    const float* Wo = (const float*)d_in[8];
    const float* bo = (const float*)d_in[9];
    float* out = (float*)d_out;
    int n = in_sizes[1];
    if (n > BMAX) n = BMAX;

    cudaFuncSetAttribute(k_main, cudaFuncAttributeMaxDynamicSharedMemorySize, SMEM_BYTES);

    int hb = (n + 255) / 256;
    k_prep<<<192, 256>>>(W1, b1, Wf, bf, W2, ls, n, hb);
    k_scatter<<<hb, 256>>>(ls, n, hb);

    int nblk = (n + CTA_SAMPLES - 1) / CTA_SAMPLES + COUNT;
    k_main<<<nblk, THREADS, SMEM_BYTES>>>(x, b2, Wo, bo, out);
}

// round 7
// speedup vs baseline: 1.1846x; 1.1846x over previous
#include <cuda_runtime.h>
#include <cuda_bf16.h>

#define L1N 16
#define DIN 1536
#define COUNT 8
#define L3N 64
#define BMAX 16384
#define CTA_SAMPLES 128
#define THREADS 512
#define CK 64                   // k per chunk
#define NCH (DIN / CK)          // 24
#define XST 68                  // x smem row stride (floats)
#define RST 20                  // reduction row stride
#define HB 64
#define NSTAGE 3

// ---- device scratch ----
__device__ float g_wsum[COUNT * DIN * L1N];   // [b][k][16]
__device__ float g_bsum[COUNT * L1N];
__device__ float g_w2p[COUNT * L3N * 32];
__device__ int   g_bh[HB * COUNT];
__device__ int   g_aoff[COUNT + 1];
__device__ int   g_order[BMAX + COUNT * CTA_SAMPLES];

// ---------------- prep: 384 blocks = 8 buckets x 48 k-tiles(32), transpose, pad W2, hist ----------------
__global__ void k_prep(const float* __restrict__ W1, const float* __restrict__ b1,
                       const float* __restrict__ Wf, const float* __restrict__ bf,
                       const float* __restrict__ W2, const int* __restrict__ ls,
                       int n, int hb) {
    __shared__ float tile[16 * 36];
    int t = threadIdx.x;
    int bucket = blockIdx.x / 48;
    int kt = blockIdx.x - bucket * 48;   // 32-k tile

    // load 16 x 32 tile, coalesced along k
#pragma unroll
    for (int r = 0; r < 2; ++r) {
        int idx = t + 256 * r;          // 0..511
        int row = idx >> 5;             // o
        int col = idx & 31;             // k in tile
        float a = W1[(size_t)(bucket * L1N + row) * DIN + kt * 32 + col]
                + Wf[(size_t)row * DIN + kt * 32 + col];
        tile[row * 36 + col] = a;
    }
    __syncthreads();

    // write transposed [k][16] as float4, fully coalesced (threads 0..127)
    if (t < 128) {
        float4* dst = (float4*)(g_wsum + (size_t)bucket * (DIN * L1N));
        int k = t >> 2;                  // 0..31
        int o4 = t & 3;
        float4 v;
        v.x = tile[(4 * o4 + 0) * 36 + k];
        v.y = tile[(4 * o4 + 1) * 36 + k];
        v.z = tile[(4 * o4 + 2) * 36 + k];
        v.w = tile[(4 * o4 + 3) * 36 + k];
        dst[(kt * 32 + k) * 4 + o4] = v;
    }

    int tidg = blockIdx.x * 256 + t;
    if (tidg < COUNT * L3N * 32) {
        int b = tidg >> 11;
        int j = (tidg >> 5) & 63;
        int i = tidg & 31;
        g_w2p[tidg] = (i < 30) ? W2[(b * L3N + j) * 30 + i] : 0.0f;
    }
    if (tidg < COUNT * L1N) {
        int b = tidg >> 4, o = tidg & 15;
        g_bsum[tidg] = b1[b * L1N + o] + bf[o];
    }
    if ((int)blockIdx.x < hb) {
        __shared__ int sh[COUNT];
        if (t < COUNT) sh[t] = 0;
        __syncthreads();
        int i = blockIdx.x * 256 + t;
        if (i < n) {
            int b = ls[i];
            unsigned act = __activemask();
            unsigned m = __match_any_sync(act, b);
            int lane = t & 31;
            int leader = __ffs(m) - 1;
            if (lane == leader) atomicAdd(&sh[b], __popc(m));
        }
        __syncthreads();
        if (t < COUNT) g_bh[blockIdx.x * COUNT + t] = sh[t];
    }
}

// ---------------- scatter with inline scan ----------------
__global__ void k_scatter(const int* __restrict__ ls, int n, int hb) {
    __shared__ int sh[HB * COUNT];
    __shared__ int s_aoff[COUNT + 1];
    __shared__ int s_cnt[COUNT];
    __shared__ int cur[COUNT];
    int t = threadIdx.x;
    for (int i = t; i < hb * COUNT; i += 256) sh[i] = g_bh[i];
    __syncthreads();
    if (t < COUNT) {
        int tot = 0;
        for (int j = 0; j < hb; ++j) tot += sh[j * COUNT + t];
        s_cnt[t] = tot;
    }
    __syncthreads();
    if (t == 0) {
        int off = 0;
        for (int b = 0; b < COUNT; ++b) {
            s_aoff[b] = off;
            off += (s_cnt[b] + CTA_SAMPLES - 1) & ~(CTA_SAMPLES - 1);
        }
        s_aoff[COUNT] = off;
        if (blockIdx.x == 0)
            for (int b = 0; b <= COUNT; ++b) g_aoff[b] = s_aoff[b];
    }
    __syncthreads();
    if (t < COUNT) {
        int run = s_aoff[t];
        for (int j = 0; j < (int)blockIdx.x; ++j) run += sh[j * COUNT + t];
        cur[t] = run;
    }
    __syncthreads();
    if (blockIdx.x == 0) {
        for (int b = 0; b < COUNT; ++b) {
            int s = s_aoff[b] + s_cnt[b];
            int e = s_aoff[b + 1];
            for (int i = s + t; i < e; i += 256) g_order[i] = -1;
        }
    }
    int i = blockIdx.x * 256 + t;
    if (i < n) {
        int b = ls[i];
        unsigned act = __activemask();
        unsigned m = __match_any_sync(act, b);
        int lane = t & 31;
        int leader = __ffs(m) - 1;
        int rank = __popc(m & ((1u << lane) - 1u));
        int base = 0;
        if (lane == leader) base = atomicAdd(&cur[b], __popc(m));
        base = __shfl_sync(act, base, leader);
        g_order[base + rank] = i;
    }
}

// ---------------- main: 512 thr, 2 samples/lane, 8 k-slices of 8, cp.async 3-stage ----------------
#define XBUF_WORDS (128 * XST)           // 8704 floats per stage
#define XS_WORDS (NSTAGE * XBUF_WORDS)   // 26112
#define SMEM_WORDS (24576 + 2048 + 16 + 64 + 64 + 128 + 512 + XS_WORDS)
#define SMEM_BYTES (SMEM_WORDS * 4)

__device__ __forceinline__ unsigned smem_u32(const void* p) {
    unsigned a;
    asm("{ .reg .u64 t; cvta.to.shared.u64 t, %1; cvt.u32.u64 %0, t; }" : "=r"(a) : "l"(p));
    return a;
}

__global__ void __launch_bounds__(THREADS, 1) k_main(const float* __restrict__ x,
                                                     const float* __restrict__ b2,
                                                     const float* __restrict__ Wo,
                                                     const float* __restrict__ bo,
                                                     float* __restrict__ out) {
    extern __shared__ float sm[];
    float* ws   = sm;                   // [k][16]; reused as red2 later
    float* w2s  = ws + 24576;           // [j][32]
    float* bs   = w2s + 2048;
    float* b2s  = bs + 16;
    float* wos  = b2s + 64;
    int* sidx_s = (int*)(wos + 64);     // 128
    float* red2 = (float*)(sidx_s + 128);  // 512
    float* xs   = red2 + 512;           // NSTAGE buffers; reused as reduction

    int tid = threadIdx.x;
    int base = blockIdx.x * CTA_SAMPLES;
    if (base >= g_aoff[COUNT]) return;

    int b = 0;
#pragma unroll
    for (int t = 1; t < COUNT; ++t)
        if (base >= g_aoff[t]) b = t;

    if (tid < 128) sidx_s[tid] = g_order[base + tid];
    __syncthreads();

    // ---- async loader: 4 regions, thread i -> row (i>>4), float4 (i&15) ----
    const char* gsrc[4];
    unsigned dsmem[4];
    unsigned xs_u = smem_u32(xs);
#pragma unroll
    for (int r = 0; r < 4; ++r) {
        int i = tid + THREADS * r;
        int s = i >> 4;
        int k4 = i & 15;
        int sv = sidx_s[s];
        gsrc[r] = (const char*)((const float4*)(x + (size_t)(sv >= 0 ? sv : 0) * DIN) + k4);
        dsmem[r] = xs_u + (unsigned)((s * XST + k4 * 4) * 4);
    }
#define ISSUE_CHUNK(c)                                                          \
    do {                                                                        \
        unsigned boff = (unsigned)(((c) % NSTAGE) * XBUF_WORDS * 4);            \
        _Pragma("unroll")                                                       \
        for (int r = 0; r < 4; ++r)                                             \
            asm volatile("cp.async.cg.shared.global [%0], [%1], 16;"            \
                         :: "r"(dsmem[r] + boff), "l"(gsrc[r] + (size_t)(c) * 256)); \
        asm volatile("cp.async.commit_group;");                                 \
    } while (0)

    ISSUE_CHUNK(0);
    ISSUE_CHUNK(1);

    // ---- stage weights while asyncs fly ----
    {
        const float4* src = (const float4*)(g_wsum + (size_t)b * (DIN * L1N));
        float4* dst = (float4*)ws;
#pragma unroll
        for (int r = 0; r < 12; ++r) dst[tid + r * THREADS] = src[tid + r * THREADS];
    }
    ((float4*)w2s)[tid] = ((const float4*)(g_w2p + (size_t)b * (L3N * 32)))[tid];
    if (tid < 16) bs[tid] = g_bsum[b * L1N + tid];
    else if (tid >= 32 && tid < 96) b2s[tid - 32] = b2[b * L3N + (tid - 32)];
    else if (tid >= 96 && tid < 160) wos[tid - 96] = Wo[b * L3N + (tid - 96)];

    // ---- consumer mapping: 2 samples/lane, 8 k-slices of 8 ----
    int wid = tid >> 5, lane = tid & 31;
    int sl = wid & 7;
    int h  = wid >> 3;
    int s0 = h * 64 + lane;
    int s1 = s0 + 32;

    unsigned long long acc[16];
#pragma unroll
    for (int i = 0; i < 16; ++i) acc[i] = 0ULL;

    const ulonglong2* wp = (const ulonglong2*)ws;

#pragma unroll 1
    for (int c = 0; c < NCH; ++c) {
        if (c + 1 < NCH) asm volatile("cp.async.wait_group 1;");
        else             asm volatile("cp.async.wait_group 0;");
        __syncthreads();
        if (c + 2 < NCH) ISSUE_CHUNK(c + 2);

        const float* xb  = xs + (c % NSTAGE) * XBUF_WORDS;
        const float* xr0 = xb + s0 * XST + sl * 8;
        const float* xr1 = xb + s1 * XST + sl * 8;
        int kg = c * CK + sl * 8;
#pragma unroll
        for (int kq = 0; kq < 8; kq += 4) {
            float4 xa = *(const float4*)(xr0 + kq);
            float4 xc = *(const float4*)(xr1 + kq);
#pragma unroll
            for (int t4 = 0; t4 < 4; ++t4) {
                float va = (t4 == 0) ? xa.x : (t4 == 1) ? xa.y : (t4 == 2) ? xa.z : xa.w;
                float vc = (t4 == 0) ? xc.x : (t4 == 1) ? xc.y : (t4 == 2) ? xc.z : xc.w;
                unsigned long long da, dc;
                asm("mov.b64 %0, {%1, %1};" : "=l"(da) : "f"(va));
                asm("mov.b64 %0, {%1, %1};" : "=l"(dc) : "f"(vc));
                const ulonglong2* wr = wp + (unsigned)(kg + kq + t4) * 4;
#pragma unroll
                for (int p = 0; p < 4; ++p) {
                    ulonglong2 wv = wr[p];
                    asm("fma.rn.f32x2 %0, %1, %2, %0;" : "+l"(acc[2*p])     : "l"(da), "l"(wv.x));
                    asm("fma.rn.f32x2 %0, %1, %2, %0;" : "+l"(acc[2*p+1])   : "l"(da), "l"(wv.y));
                    asm("fma.rn.f32x2 %0, %1, %2, %0;" : "+l"(acc[8+2*p])   : "l"(dc), "l"(wv.x));
                    asm("fma.rn.f32x2 %0, %1, %2, %0;" : "+l"(acc[8+2*p+1]) : "l"(dc), "l"(wv.y));
                }
            }
        }
    }
    __syncthreads();

    // ---- 8-way k reduction in xs (stride RST, 16B aligned) ----
    float* red = xs;  // 8*128*20 = 20480 <= 26112
    {
        float* br0 = red + (sl * 128 + s0) * RST;
        float* br1 = red + (sl * 128 + s1) * RST;
#pragma unroll
        for (int p = 0; p < 8; ++p) {
            float lo, hi;
            asm("mov.b64 {%0, %1}, %2;" : "=f"(lo), "=f"(hi) : "l"(acc[p]));
            br0[2 * p] = lo; br0[2 * p + 1] = hi;
            asm("mov.b64 {%0, %1}, %2;" : "=f"(lo), "=f"(hi) : "l"(acc[8 + p]));
            br1[2 * p] = lo; br1[2 * p + 1] = hi;
        }
    }
    __syncthreads();

    // ---- tail: 4 j-groups x 128 samples ----
    int s2 = tid & 127;
    int jg = tid >> 7;
    float l1[16];
#pragma unroll
    for (int o = 0; o < 16; o += 4) {
        float4 v = *(const float4*)(bs + o);
#pragma unroll
        for (int q = 0; q < 8; ++q) {
            float4 r4 = *(const float4*)(red + (q * 128 + s2) * RST + o);
            v.x += r4.x; v.y += r4.y; v.z += r4.z; v.w += r4.w;
        }
        l1[o] = v.x; l1[o + 1] = v.y; l1[o + 2] = v.z; l1[o + 3] = v.w;
    }

    const float C = 127.0f / 128.0f;
    float lx[32];
#pragma unroll
    for (int i = 0; i < 15; ++i) {
        float v = l1[i];
        float sq = (v * v) * C;
        lx[i]      = fminf(fmaxf(sq, 0.0f), 1.0f);
        lx[15 + i] = fminf(fmaxf(v, 0.0f), 1.0f);
    }
    lx[30] = 0.0f;
    lx[31] = 0.0f;

    float l3p = 0.0f;
#pragma unroll 2
    for (int jj = 0; jj < 16; ++jj) {
        int j = jg * 16 + jj;
        float ssum = b2s[j];
        const float4* wr2 = (const float4*)(w2s + j * 32);
#pragma unroll
        for (int p = 0; p < 8; ++p) {
            float4 wv = wr2[p];
            ssum = fmaf(lx[4 * p + 0], wv.x, ssum);
            ssum = fmaf(lx[4 * p + 1], wv.y, ssum);
            ssum = fmaf(lx[4 * p + 2], wv.z, ssum);
            ssum = fmaf(lx[4 * p + 3], wv.w, ssum);
        }
        float sc = fminf(fmaxf(ssum, 0.0f), 1.0f);
        l3p = fmaf(sc, wos[j], l3p);
    }
    red2[jg * 128 + s2] = l3p;
    __syncthreads();

    if (tid < 128) {
        int sv = sidx_s[tid];
        if (sv >= 0) {
            float l3 = red2[tid] + red2[128 + tid] + red2[256 + tid] + red2[384 + tid];
            out[sv] = l3 + bo[b] + l1[15];
        }
    }
}

// ---------------- launch ----------------
extern "C" void kernel_launch(void* const* d_in, const int* in_sizes, int n_in,
                              void* d_out, int out_size) {
    const float* x  = (const float*)d_in[0];
    const int*   ls = (const int*)d_in[1];
    const float* W1 = (const float*)d_in[2];
    const float* b1 = (const float*)d_in[3];
    const float* Wf = (const float*)d_in[4];
    const float* bf = (const float*)d_in[5];
    const float* W2 = (const float*)d_in[6];
    const float* b2 = (const float*)d_in[7];
    const float* Wo = (const float*)d_in[8];
    const float* bo = (const float*)d_in[9];
    float* out = (float*)d_out;
    int n = in_sizes[1];
    if (n > BMAX) n = BMAX;

    cudaFuncSetAttribute(k_main, cudaFuncAttributeMaxDynamicSharedMemorySize, SMEM_BYTES);

    int hb = (n + 255) / 256;
    k_prep<<<384, 256>>>(W1, b1, Wf, bf, W2, ls, n, hb);
    k_scatter<<<hb, 256>>>(ls, n, hb);

    int nblk = (n + CTA_SAMPLES - 1) / CTA_SAMPLES + COUNT;
    k_main<<<nblk, THREADS, SMEM_BYTES>>>(x, b2, Wo, bo, out);
}